// round 1
// baseline (speedup 1.0000x reference)
#include <cuda_runtime.h>
#include <cuda_bf16.h>
#include <cstdint>

// Problem constants
#define B   2
#define N   512
#define MV  512
#define DIN 256
#define H   16
#define DOUT 128
#define LN_EPS 1e-5f

// Scratch: proj = [B*N][32] (a = cols 0..15, bq = cols 16..31); T = [B][M][16 p][128 d]
__device__ float g_proj[B * N * 2 * H];            // 128 KB
__device__ float g_T[B * MV * H * DOUT];           // 8 MB

// packed f32x2 FMA: d = a*b + c lanewise on two fp32 packed in a 64-bit reg
#define FMA_F32X2(d_, a_, b_, c_) \
    asm("fma.rn.f32x2 %0, %1, %2, %3;" : "=l"(d_) : "l"(a_), "l"(b_), "l"(c_))

// ---------------------------------------------------------------------------
// Kernel 1: LayerNorm + input projection.  One block per row (B*N = 1024 rows).
// proj[r][j] = b_in[j] + sum_i xhat[r][i]*W_in[i][j]
// ---------------------------------------------------------------------------
__global__ __launch_bounds__(256) void k_proj(
    const float* __restrict__ feats, const float* __restrict__ gamma,
    const float* __restrict__ beta,  const float* __restrict__ W_in,
    const float* __restrict__ b_in,  float* __restrict__ proj)
{
    int r = blockIdx.x;            // 0..1023
    int t = threadIdx.x;           // 0..255
    __shared__ float xs[DIN];
    __shared__ float ws[8], ws2[8];
    __shared__ float ps[8][32];

    float v = feats[r * DIN + t];
    float s = v, s2 = v * v;
    #pragma unroll
    for (int o = 16; o; o >>= 1) {
        s  += __shfl_xor_sync(0xFFFFFFFFu, s,  o);
        s2 += __shfl_xor_sync(0xFFFFFFFFu, s2, o);
    }
    if ((t & 31) == 0) { ws[t >> 5] = s; ws2[t >> 5] = s2; }
    __syncthreads();
    float ts = 0.f, ts2 = 0.f;
    #pragma unroll
    for (int i = 0; i < 8; i++) { ts += ws[i]; ts2 += ws2[i]; }
    float mu  = ts * (1.f / DIN);
    float var = ts2 * (1.f / DIN) - mu * mu;
    float rs  = rsqrtf(var + LN_EPS);
    xs[t] = (v - mu) * rs * gamma[t] + beta[t];
    __syncthreads();

    int j = t & 31, seg = t >> 5;
    float acc = 0.f;
    #pragma unroll 8
    for (int i = seg * 32; i < seg * 32 + 32; i++)
        acc = fmaf(xs[i], W_in[i * 32 + j], acc);
    ps[seg][j] = acc;
    __syncthreads();
    if (seg == 0) {
        float tot = b_in[j];
        #pragma unroll
        for (int i = 0; i < 8; i++) tot += ps[i][j];
        proj[r * 32 + j] = tot;
    }
}

// ---------------------------------------------------------------------------
// Kernel 2: T[b][m][p][d] = sum_q W_out[d][p*16+q] * bq[b][m][q]
// Grid: B * (M/8) = 128 blocks, 256 threads. Each block: 8 m values.
// ---------------------------------------------------------------------------
__global__ __launch_bounds__(256) void k_T(
    const float* __restrict__ proj, const float* __restrict__ W_out,
    float* __restrict__ T)
{
    int bm = blockIdx.x;           // 0..127
    int b  = bm >> 6;              // 64 m-groups per b
    int m0 = (bm & 63) * 8;
    int t  = threadIdx.x;

    __shared__ float bq[8][16];
    if (t < 128) {
        int mm = t >> 4, q = t & 15;
        bq[mm][q] = proj[(b * N + m0 + mm) * 32 + 16 + q];
    }
    __syncthreads();

    int d = t & 127, ph = t >> 7;  // ph selects p-range
    #pragma unroll
    for (int pi = 0; pi < 8; pi++) {
        int p = ph * 8 + pi;
        const float4* wp = (const float4*)&W_out[d * 256 + p * 16];
        float4 w0 = wp[0], w1 = wp[1], w2 = wp[2], w3 = wp[3];
        float w[16] = { w0.x,w0.y,w0.z,w0.w, w1.x,w1.y,w1.z,w1.w,
                        w2.x,w2.y,w2.z,w2.w, w3.x,w3.y,w3.z,w3.w };
        #pragma unroll
        for (int mm = 0; mm < 8; mm++) {
            float acc = 0.f;
            #pragma unroll
            for (int q = 0; q < 16; q++) acc = fmaf(w[q], bq[mm][q], acc);
            T[(((b * N) + (m0 + mm)) * H + p) * DOUT + d] = acc;
        }
    }
}

// ---------------------------------------------------------------------------
// Kernel 3: main contraction.
// Job = (b, m, n-quarter of 128).  Grid = 2*512*4 = 4096 blocks, 256 threads.
// Thread tile: 8 n  x  8 d (4 f32x2 pairs), K-loop over p (16), packed FFMA2.
// out[b,n,m,d] = b_out[d] + sum_p a[b,n,p] * T[b,m,p,d]
// ---------------------------------------------------------------------------
__global__ __launch_bounds__(256, 2) void k_main(
    const float* __restrict__ proj, const float* __restrict__ Tg,
    const float* __restrict__ b_out, float* __restrict__ out)
{
    int job = blockIdx.x;
    int b   = job >> 11;
    int m   = (job >> 2) & 511;
    int n0  = (job & 3) * 128;
    int t   = threadIdx.x;

    __shared__ float Ts[H * DOUT];                 // 8 KB, chunk-swizzled
    __shared__ unsigned long long As[H * 128];     // 16 KB, [p][n] as (v,v) packs

    // ---- stage T (swizzle: 16B chunk c -> c ^ ((c>>3)&1), spreads banks) ----
    {
        const float* Tsrc = Tg + (size_t)(b * N + m) * (H * DOUT);
        #pragma unroll
        for (int i = t; i < H * DOUT; i += 256) {
            int p = i >> 7, d = i & 127;
            int c  = d >> 2;
            int pc = c ^ ((c >> 3) & 1);
            Ts[p * 128 + pc * 4 + (d & 3)] = Tsrc[i];
        }
    }
    // ---- stage a, pre-duplicated into f32x2 packs, layout [p][n] ----
    {
        int n  = t >> 1;
        int hp = (t & 1) * 8;
        const float* pr = proj + (size_t)(b * N + n0 + n) * 32 + hp;
        float4 v0 = *(const float4*)pr;
        float4 v1 = *(const float4*)(pr + 4);
        float vv[8] = { v0.x,v0.y,v0.z,v0.w, v1.x,v1.y,v1.z,v1.w };
        #pragma unroll
        for (int k = 0; k < 8; k++) {
            unsigned int ui = __float_as_uint(vv[k]);
            As[(hp + k) * 128 + n] = (unsigned long long)ui |
                                     ((unsigned long long)ui << 32);
        }
    }
    __syncthreads();

    int dg = t & 15;               // d-group: d = dg*8 .. dg*8+7
    int ng = t >> 4;               // n-group: n = n0 + ng*8 .. +7
    int d8 = dg * 8;
    int bitb = (dg >> 2) & 1;      // swizzle bit for this thread's chunks

    // acc init = b_out
    unsigned long long acc[8][4];
    {
        const ulonglong2* bp = (const ulonglong2*)(b_out + d8);
        ulonglong2 b01 = bp[0], b23 = bp[1];
        #pragma unroll
        for (int j = 0; j < 8; j++) {
            acc[j][0] = b01.x; acc[j][1] = b01.y;
            acc[j][2] = b23.x; acc[j][3] = b23.y;
        }
    }

    #pragma unroll
    for (int p = 0; p < 16; p++) {
        // T packs for this thread's 8 d's (logical chunks 2dg, 2dg+1)
        ulonglong2 ua = *(const ulonglong2*)&Ts[p * 128 + (2 * dg + bitb) * 4];
        ulonglong2 ub = *(const ulonglong2*)&Ts[p * 128 + (2 * dg + (bitb ^ 1)) * 4];
        unsigned long long tv[4] = { ua.x, ua.y, ub.x, ub.y };
        // a packs for this thread's 8 n's (contiguous -> 4x LDS.128, broadcast)
        const ulonglong2* ap = (const ulonglong2*)&As[p * 128 + ng * 8];
        ulonglong2 a01 = ap[0], a23 = ap[1], a45 = ap[2], a67 = ap[3];
        unsigned long long av[8] = { a01.x, a01.y, a23.x, a23.y,
                                     a45.x, a45.y, a67.x, a67.y };
        #pragma unroll
        for (int j = 0; j < 8; j++)
            #pragma unroll
            for (int k = 0; k < 4; k++)
                FMA_F32X2(acc[j][k], av[j], tv[k], acc[j][k]);
    }

    // ---- store: 8 n rows x 32B each, fully coalesced across the warp ----
    #pragma unroll
    for (int j = 0; j < 8; j++) {
        size_t n = (size_t)(n0 + ng * 8 + j);
        float* op = out + (((size_t)b * N + n) * MV + m) * DOUT + d8;
        ((ulonglong2*)op)[0] = make_ulonglong2(acc[j][0], acc[j][1]);
        ((ulonglong2*)op)[1] = make_ulonglong2(acc[j][2], acc[j][3]);
    }
}

// ---------------------------------------------------------------------------
extern "C" void kernel_launch(void* const* d_in, const int* in_sizes, int n_in,
                              void* d_out, int out_size)
{
    const float* feats  = (const float*)d_in[0];
    const float* gamma  = (const float*)d_in[1];
    const float* beta   = (const float*)d_in[2];
    const float* W_in   = (const float*)d_in[3];
    const float* b_in   = (const float*)d_in[4];
    const float* W_out  = (const float*)d_in[5];
    const float* b_out  = (const float*)d_in[6];
    float* out = (float*)d_out;

    float* proj; cudaGetSymbolAddress((void**)&proj, g_proj);
    float* T;    cudaGetSymbolAddress((void**)&T,    g_T);

    k_proj<<<B * N, 256>>>(feats, gamma, beta, W_in, b_in, proj);
    k_T<<<B * (MV / 8), 256>>>(proj, W_out, T);
    k_main<<<B * MV * 4, 256>>>(proj, T, b_out, out);
}